// round 5
// baseline (speedup 1.0000x reference)
#include <cuda_runtime.h>
#include <cstdint>

typedef unsigned long long ull;

#define MULQ 16
#define NPAIR 136
#define SLICES 4
#define NT 256
#define NODES_PER_CTA 256
#define XS 260

// g_W layout: [0, 15232) = per (p, s): 28 floats {wy[4], ws[4], w112[4w'x5k]}
//             [15232, 19328) = w101 [u][v][w] * A101
#define OFF_W1   15232
#define W_TOTAL  19328
#define SMEM_FLOATS (W_TOTAL + 64 * XS)
#define SMEM_BYTES  (SMEM_FLOATS * 4)

__device__ __align__(16) float g_W[W_TOTAL];

// ---------------- f32x2 helpers (sm_103a packed fp32) ----------------
__device__ __forceinline__ ull pack2(float a, float b) {
    ull r;
    asm("mov.b64 %0, {%1, %2};" : "=l"(r) : "f"(a), "f"(b));
    return r;
}
__device__ __forceinline__ void fma2(ull& acc, ull a, ull b) {
    asm("fma.rn.f32x2 %0, %1, %2, %0;" : "+l"(acc) : "l"(a), "l"(b));
}
__device__ __forceinline__ ull mul2(ull a, ull b) {
    ull r;
    asm("mul.rn.f32x2 %0, %1, %2;" : "=l"(r) : "l"(a), "l"(b));
    return r;
}
__device__ __forceinline__ ull add2(ull a, ull b) {
    ull r;
    asm("add.rn.f32x2 %0, %1, %2;" : "=l"(r) : "l"(a), "l"(b));
    return r;
}
__device__ __forceinline__ ull sub2(ull a, ull b) {
    ull r;
    asm("sub.rn.f32x2 %0, %1, %2;" : "=l"(r) : "l"(a), "l"(b));
    return r;
}
__device__ __forceinline__ float2 unpack2(ull v) {
    float2 r;
    asm("mov.b64 {%0, %1}, %2;" : "=f"(r.x), "=f"(r.y) : "l"(v));
    return r;
}

__device__ __forceinline__ void decode_pair(int p, int& u, int& v) {
    int uu = 0, r = p;
    while (r >= MULQ - uu) { r -= MULQ - uu; ++uu; }
    u = uu;
    v = uu + r;
}

// ---------------- weight prep ----------------
__global__ void prep_kernel(const float* __restrict__ w000, const float* __restrict__ w101,
                            const float* __restrict__ w110, const float* __restrict__ w112) {
    const float A000  = 0.044194173824159216f;  // sqrt(1/512)
    const float A110  = 0.025515518153991442f;  // A000/sqrt(3)
    const float A101  = 0.0625f;
    const float S112A = 0.044194173824159216f;  // A112/sqrt(10)
    const float S112B = 0.025515518153991442f;  // A112/sqrt(30)

    const int tid = blockIdx.x * blockDim.x + threadIdx.x;
    const int nth = gridDim.x * blockDim.x;

    // per (p, s): 28 floats: [wy 4][ws 4][w112 20 (w'*5+k)]
    for (int idx = tid; idx < NPAIR * SLICES * 28; idx += nth) {
        int p = idx / 112;
        int r = idx - p * 112;
        int s = r / 28;
        int j = r - s * 28;
        int u, v;
        decode_pair(p, u, v);
        float val;
        if (j < 4) {
            int w = 4 * s + j;
            float c = w000[u * 256 + v * 16 + w];
            if (u != v) c += w000[v * 256 + u * 16 + w];
            val = c * A000;
        } else if (j < 8) {
            int w = 4 * s + (j - 4);
            float c = w110[u * 256 + v * 16 + w];
            if (u != v) c += w110[v * 256 + u * 16 + w];
            val = c * A110;
        } else {
            int jj = j - 8;
            int wp = jj / 5, k = jj - 5 * wp;
            int w = 4 * s + wp;
            float c = w112[u * 256 + v * 16 + w];
            if (u != v) c += w112[v * 256 + u * 16 + w];
            val = c * (k == 4 ? S112B : S112A);
        }
        g_W[idx] = val;
    }
    // w101 natural layout [u][v][w] * A101
    for (int idx = tid; idx < 4096; idx += nth) {
        g_W[OFF_W1 + idx] = w101[idx] * A101;
    }
}

// ---------------- main kernel: thread = 4 nodes x w-quarter, f32x2 over node pairs ----------------
__global__ void __launch_bounds__(NT)
tsq_kernel(const float* __restrict__ nf, const float* __restrict__ nm,
           float* __restrict__ out, int nnodes) {
    extern __shared__ float smem[];
    float* sWP = smem;                 // 15232 floats
    float* sW1 = smem + OFF_W1;        // 4096 floats
    float* sX  = smem + W_TOTAL;       // 64 x XS, node-major rows
    const int t = threadIdx.x;

    // stage weights
    {
        const float4* src = (const float4*)g_W;
        float4* dst = (float4*)smem;
        for (int i = t; i < W_TOTAL / 4; i += NT) dst[i] = src[i];
    }
    // stage x = nf + nm, transposed to sX[comp * XS + node]
    {
        const int base4 = blockIdx.x * (NODES_PER_CTA * 16);
        const int limit4 = nnodes * 16;
        const float4* a4 = (const float4*)nf;
        const float4* b4 = (const float4*)nm;
        for (int i = t; i < NODES_PER_CTA * 16; i += NT) {
            int gi = base4 + i;
            float4 a = make_float4(0.f, 0.f, 0.f, 0.f), b = a;
            if (gi < limit4) { a = a4[gi]; b = b4[gi]; }
            int node = i >> 4, fq = (i & 15) << 2;
            sX[(fq + 0) * XS + node] = a.x + b.x;
            sX[(fq + 1) * XS + node] = a.y + b.y;
            sX[(fq + 2) * XS + node] = a.z + b.z;
            sX[(fq + 3) * XS + node] = a.w + b.w;
        }
    }
    __syncthreads();

    const int s   = t >> 6;        // w-quarter slice (warp-uniform)
    const int ng  = t & 63;        // node group
    const int nl0 = ng * 4;        // first local node

    const float* xb = sX + nl0;

    ull acc0[8];   // [w'(4)][half(2)]
    ull acc2[40];  // [w'*5+k (20)][half(2)]
#pragma unroll
    for (int j = 0; j < 8; j++) acc0[j] = 0ull;
#pragma unroll
    for (int j = 0; j < 40; j++) acc2[j] = 0ull;

    int p = 0;
#pragma unroll 1
    for (int u = 0; u < MULQ; ++u) {
        const ulonglong2 A0 = *(const ulonglong2*)(xb + u * XS);
        const ulonglong2 AX = *(const ulonglong2*)(xb + (MULQ + 3 * u + 0) * XS);
        const ulonglong2 AY = *(const ulonglong2*)(xb + (MULQ + 3 * u + 1) * XS);
        const ulonglong2 AZ = *(const ulonglong2*)(xb + (MULQ + 3 * u + 2) * XS);
#pragma unroll 1
        for (int v = u; v < MULQ; ++v, ++p) {
            const ulonglong2 B0 = *(const ulonglong2*)(xb + v * XS);
            const ulonglong2 BX = *(const ulonglong2*)(xb + (MULQ + 3 * v + 0) * XS);
            const ulonglong2 BY = *(const ulonglong2*)(xb + (MULQ + 3 * v + 1) * XS);
            const ulonglong2 BZ = *(const ulonglong2*)(xb + (MULQ + 3 * v + 2) * XS);

            // basis, low half (nodes 0,1)
            ull yl = mul2(A0.x, B0.x);
            ull m00 = mul2(AX.x, BX.x), m01 = mul2(AX.x, BY.x), m02 = mul2(AX.x, BZ.x);
            ull m10 = mul2(AY.x, BX.x), m11 = mul2(AY.x, BY.x), m12 = mul2(AY.x, BZ.x);
            ull m20 = mul2(AZ.x, BX.x), m21 = mul2(AZ.x, BY.x), m22 = mul2(AZ.x, BZ.x);
            ull hl = add2(m00, m11);
            ull sl = add2(hl, m22);
            ull T0l = add2(m01, m10), T1l = add2(m02, m20), T2l = add2(m12, m21);
            ull T3l = sub2(m00, m11);
            ull T4l = sub2(add2(m22, m22), hl);
            // basis, high half (nodes 2,3)
            ull yh = mul2(A0.y, B0.y);
            ull n00 = mul2(AX.y, BX.y), n01 = mul2(AX.y, BY.y), n02 = mul2(AX.y, BZ.y);
            ull n10 = mul2(AY.y, BX.y), n11 = mul2(AY.y, BY.y), n12 = mul2(AY.y, BZ.y);
            ull n20 = mul2(AZ.y, BX.y), n21 = mul2(AZ.y, BY.y), n22 = mul2(AZ.y, BZ.y);
            ull hh = add2(n00, n11);
            ull sh = add2(hh, n22);
            ull T0h = add2(n01, n10), T1h = add2(n02, n20), T2h = add2(n12, n21);
            ull T3h = sub2(n00, n11);
            ull T4h = sub2(add2(n22, n22), hh);

            const float4* wq = (const float4*)(sWP + (p * SLICES + s) * 28);
            const float4 qy = wq[0];
            const float4 qs = wq[1];
            ull d;
            d = pack2(qy.x, qy.x); fma2(acc0[0], d, yl); fma2(acc0[1], d, yh);
            d = pack2(qy.y, qy.y); fma2(acc0[2], d, yl); fma2(acc0[3], d, yh);
            d = pack2(qy.z, qy.z); fma2(acc0[4], d, yl); fma2(acc0[5], d, yh);
            d = pack2(qy.w, qy.w); fma2(acc0[6], d, yl); fma2(acc0[7], d, yh);
            d = pack2(qs.x, qs.x); fma2(acc0[0], d, sl); fma2(acc0[1], d, sh);
            d = pack2(qs.y, qs.y); fma2(acc0[2], d, sl); fma2(acc0[3], d, sh);
            d = pack2(qs.z, qs.z); fma2(acc0[4], d, sl); fma2(acc0[5], d, sh);
            d = pack2(qs.w, qs.w); fma2(acc0[6], d, sl); fma2(acc0[7], d, sh);

            const float4 qa = wq[2], qb = wq[3], qc = wq[4], qd = wq[5], qe = wq[6];
            const float wv[20] = {qa.x, qa.y, qa.z, qa.w, qb.x, qb.y, qb.z, qb.w,
                                  qc.x, qc.y, qc.z, qc.w, qd.x, qd.y, qd.z, qd.w,
                                  qe.x, qe.y, qe.z, qe.w};
            const ull TL[5] = {T0l, T1l, T2l, T3l, T4l};
            const ull TH[5] = {T0h, T1h, T2h, T3h, T4h};
#pragma unroll
            for (int m = 0; m < 20; ++m) {
                const int k = m % 5;
                d = pack2(wv[m], wv[m]);
                fma2(acc2[2 * m], d, TL[k]);
                fma2(acc2[2 * m + 1], d, TH[k]);
            }
        }
    }

    // ---- store out0 + out2 (frees 48 ull of accumulators before out1 phase) ----
    const int nodeBase = blockIdx.x * NODES_PER_CTA + nl0;
#pragma unroll
    for (int j = 0; j < 4; ++j) {
        const int node = nodeBase + j;
        if (node >= nnodes) break;
        float* dst = out + (size_t)node * 144;
        const int h = j >> 1;
        const int odd = j & 1;
        {
            float o0[4];
#pragma unroll
            for (int w = 0; w < 4; ++w) {
                float2 vv = unpack2(acc0[w * 2 + h]);
                o0[w] = odd ? vv.y : vv.x;
            }
            *(float4*)(dst + 4 * s) = make_float4(o0[0], o0[1], o0[2], o0[3]);
        }
        {
            float o2[20];
#pragma unroll
            for (int m = 0; m < 20; ++m) {
                float2 vv = unpack2(acc2[2 * m + h]);
                o2[m] = odd ? vv.y : vv.x;
            }
            float4* p2 = (float4*)(dst + 64 + 20 * s);
#pragma unroll
            for (int i = 0; i < 5; ++i)
                p2[i] = make_float4(o2[4 * i], o2[4 * i + 1], o2[4 * i + 2], o2[4 * i + 3]);
        }
    }

    // ---- out1: out1[w,k](n) = sum_u x1[u,k](n) * G[u,w](n),
    //      G[u,w](n) = sum_v A101*w101[u,v,w] * x0[v](n) ----
    ull acc1[24];  // [(w'*3+k) (12)][half(2)]
#pragma unroll
    for (int j = 0; j < 24; j++) acc1[j] = 0ull;
#pragma unroll 1
    for (int u = 0; u < MULQ; ++u) {
        ull G[8];
#pragma unroll
        for (int j = 0; j < 8; j++) G[j] = 0ull;
        const float* w1row = sW1 + u * 256 + 4 * s;
#pragma unroll 4
        for (int v = 0; v < MULQ; ++v) {
            const float4 qw = *(const float4*)(w1row + v * 16);
            const ulonglong2 X0 = *(const ulonglong2*)(xb + v * XS);
            ull d;
            d = pack2(qw.x, qw.x); fma2(G[0], d, X0.x); fma2(G[1], d, X0.y);
            d = pack2(qw.y, qw.y); fma2(G[2], d, X0.x); fma2(G[3], d, X0.y);
            d = pack2(qw.z, qw.z); fma2(G[4], d, X0.x); fma2(G[5], d, X0.y);
            d = pack2(qw.w, qw.w); fma2(G[6], d, X0.x); fma2(G[7], d, X0.y);
        }
        const ulonglong2 K0 = *(const ulonglong2*)(xb + (MULQ + 3 * u + 0) * XS);
        const ulonglong2 K1 = *(const ulonglong2*)(xb + (MULQ + 3 * u + 1) * XS);
        const ulonglong2 K2 = *(const ulonglong2*)(xb + (MULQ + 3 * u + 2) * XS);
#pragma unroll
        for (int w = 0; w < 4; ++w) {
            fma2(acc1[(w * 3 + 0) * 2 + 0], G[w * 2 + 0], K0.x);
            fma2(acc1[(w * 3 + 0) * 2 + 1], G[w * 2 + 1], K0.y);
            fma2(acc1[(w * 3 + 1) * 2 + 0], G[w * 2 + 0], K1.x);
            fma2(acc1[(w * 3 + 1) * 2 + 1], G[w * 2 + 1], K1.y);
            fma2(acc1[(w * 3 + 2) * 2 + 0], G[w * 2 + 0], K2.x);
            fma2(acc1[(w * 3 + 2) * 2 + 1], G[w * 2 + 1], K2.y);
        }
    }

    // ---- store out1 ----
#pragma unroll
    for (int j = 0; j < 4; ++j) {
        const int node = nodeBase + j;
        if (node >= nnodes) break;
        float* dst = out + (size_t)node * 144;
        const int h = j >> 1;
        const int odd = j & 1;
        float o1[12];
#pragma unroll
        for (int m = 0; m < 12; ++m) {
            float2 vv = unpack2(acc1[2 * m + h]);
            o1[m] = odd ? vv.y : vv.x;
        }
        float4* p1 = (float4*)(dst + 16 + 12 * s);
        p1[0] = make_float4(o1[0], o1[1], o1[2], o1[3]);
        p1[1] = make_float4(o1[4], o1[5], o1[6], o1[7]);
        p1[2] = make_float4(o1[8], o1[9], o1[10], o1[11]);
    }
}

extern "C" void kernel_launch(void* const* d_in, const int* in_sizes, int n_in,
                              void* d_out, int out_size) {
    const float* nf   = (const float*)d_in[0];
    const float* nm   = (const float*)d_in[1];
    const float* w000 = (const float*)d_in[2];
    const float* w101 = (const float*)d_in[3];
    const float* w110 = (const float*)d_in[4];
    const float* w112 = (const float*)d_in[5];
    const int nnodes = in_sizes[0] / 64;

    prep_kernel<<<32, 256>>>(w000, w101, w110, w112);

    cudaFuncSetAttribute(tsq_kernel, cudaFuncAttributeMaxDynamicSharedMemorySize, SMEM_BYTES);
    const int grid = (nnodes + NODES_PER_CTA - 1) / NODES_PER_CTA;
    tsq_kernel<<<grid, NT, SMEM_BYTES>>>(nf, nm, (float*)d_out, nnodes);
}